// round 1
// baseline (speedup 1.0000x reference)
#include <cuda_runtime.h>
#include <cuda_bf16.h>
#include <math.h>

#define NN 131072
#define FN 64
#define FF 16
#define HH 128
#define EE 2097152
#define BB 256
#define LL 32

// ---------------- scratch (device globals; no allocations allowed) ----------
__device__ float g_agg1[NN * FN];      // 32 MB
__device__ float g_cnt[NN];
__device__ float g_h1[NN * HH];        // 64 MB
__device__ float g_agg2[NN * HH];      // 64 MB
__device__ float g_nemb[NN * HH];      // 64 MB
__device__ float g_gsum[BB * HH];
__device__ float g_gcnt[BB];
__device__ float g_Xg[BB * LL * 4 * HH];   // 16 MB  (precomputed x@Wih^T + bias)
__device__ float g_WT[HH * 4 * HH];        // Whh transposed [k][j]
__device__ float g_pemb[BB * HH];

// ---------------- helpers ---------------------------------------------------
__device__ __forceinline__ void red4(float* p, float4 v) {
    asm volatile("red.global.add.v4.f32 [%0], {%1,%2,%3,%4};"
                 :: "l"(p), "f"(v.x), "f"(v.y), "f"(v.z), "f"(v.w) : "memory");
}
__device__ __forceinline__ float sigf(float x) { return 1.0f / (1.0f + __expf(-x)); }

// ---------------- zero scratch ----------------------------------------------
__global__ void zero_scratch() {
    unsigned i = blockIdx.x * 256u + threadIdx.x;      // grid covers 16.7M
    if (i < NN * FN)  g_agg1[i] = 0.0f;
    if (i < (unsigned)NN * HH) g_agg2[i] = 0.0f;
    if (i < NN)       g_cnt[i] = 0.0f;
    if (i < BB * HH)  g_gsum[i] = 0.0f;
    if (i < BB)       g_gcnt[i] = 0.0f;
}

// ---------------- edge scatter, layer 1 (x: 64 feats) -----------------------
__global__ void scatter1_kernel(const int* __restrict__ ei, const float* __restrict__ x) {
    unsigned tid = blockIdx.x * 256u + threadIdx.x;    // E*16 threads
    unsigned e = tid >> 4, c = tid & 15;
    int src = __ldg(&ei[e]);
    int dst = __ldg(&ei[EE + e]);
    float4 v = *(const float4*)(x + (size_t)src * FN + c * 4);
    red4(g_agg1 + (size_t)dst * FN + c * 4, v);
    if (c == 0) atomicAdd(&g_cnt[dst], 1.0f);
}

// ---------------- edge scatter, layer 2 (h1: 128 feats) ---------------------
__global__ void scatter2_kernel(const int* __restrict__ ei) {
    unsigned tid = blockIdx.x * 256u + threadIdx.x;    // E*32 threads
    unsigned e = tid >> 5, c = tid & 31;
    int src = __ldg(&ei[e]);
    int dst = __ldg(&ei[EE + e]);
    float4 v = *(const float4*)(g_h1 + (size_t)src * HH + c * 4);
    red4(g_agg2 + (size_t)dst * HH + c * 4, v);
}

// ---------------- SAGE layer 1 GEMM: h1 = relu([mean|x] @ [Wl1;Wr1]^T + b1) -
// 64-row tiles, K=128, 128 cols. thread: 8 rows x 4 cols. sW padded to 129.
__global__ void gemm1_kernel(const float* __restrict__ x, const float* __restrict__ Wl,
                             const float* __restrict__ Wr, const float* __restrict__ b1) {
    extern __shared__ float sm[];
    float* sW = sm;                 // [128][129]
    float* sIn = sm + 128 * 129;    // [64][128]
    int t = threadIdx.x;
    #pragma unroll 4
    for (int i = 0; i < 64; i++) {
        int idx = t + i * 256;
        int j = idx >> 7, k = idx & 127;
        float v = (k < 64) ? Wl[j * 64 + k] : Wr[j * 64 + (k - 64)];
        sW[k * 129 + j] = v;
    }
    int j0 = t & 31, r0 = (t >> 5) * 8;
    float bias[4];
    #pragma unroll
    for (int i = 0; i < 4; i++) bias[i] = __ldg(&b1[j0 + 32 * i]);

    for (int tile = blockIdx.x; tile < NN / 64; tile += gridDim.x) {
        int row0 = tile * 64;
        __syncthreads();
        #pragma unroll
        for (int i = 0; i < 4; i++) {
            int idx = t + i * 256;          // 1024 quads = 64 rows * 16 quads
            int r = idx >> 4, kq = idx & 15;
            float inv = 1.0f / fmaxf(g_cnt[row0 + r], 1.0f);
            float4 a = *(const float4*)(g_agg1 + (size_t)(row0 + r) * FN + kq * 4);
            a.x *= inv; a.y *= inv; a.z *= inv; a.w *= inv;
            *(float4*)(sIn + r * 128 + kq * 4) = a;
            float4 xv = *(const float4*)(x + (size_t)(row0 + r) * FN + kq * 4);
            *(float4*)(sIn + r * 128 + 64 + kq * 4) = xv;
        }
        __syncthreads();
        float acc[8][4];
        #pragma unroll
        for (int r = 0; r < 8; r++)
            #pragma unroll
            for (int i = 0; i < 4; i++) acc[r][i] = bias[i];
        #pragma unroll 4
        for (int k = 0; k < 128; k++) {
            float w0 = sW[k * 129 + j0];
            float w1 = sW[k * 129 + j0 + 32];
            float w2 = sW[k * 129 + j0 + 64];
            float w3 = sW[k * 129 + j0 + 96];
            #pragma unroll
            for (int r = 0; r < 8; r++) {
                float a = sIn[(r0 + r) * 128 + k];
                acc[r][0] += a * w0; acc[r][1] += a * w1;
                acc[r][2] += a * w2; acc[r][3] += a * w3;
            }
        }
        #pragma unroll
        for (int r = 0; r < 8; r++)
            #pragma unroll
            for (int i = 0; i < 4; i++)
                g_h1[(size_t)(row0 + r0 + r) * HH + j0 + 32 * i] = fmaxf(acc[r][i], 0.0f);
    }
}

// ---------------- SAGE layer 2 GEMM: nemb = relu([mean2|h1] @ [Wl2;Wr2]^T + b2)
__global__ void gemm2_kernel(const float* __restrict__ Wl, const float* __restrict__ Wr,
                             const float* __restrict__ b2) {
    extern __shared__ float sm[];
    float* sW = sm;                 // [256][129]
    float* sIn = sm + 256 * 129;    // [64][256]
    int t = threadIdx.x;
    #pragma unroll 4
    for (int i = 0; i < 128; i++) {
        int idx = t + i * 256;
        int j = idx >> 8, k = idx & 255;
        float v = (k < 128) ? Wl[j * 128 + k] : Wr[j * 128 + (k - 128)];
        sW[k * 129 + j] = v;
    }
    int j0 = t & 31, r0 = (t >> 5) * 8;
    float bias[4];
    #pragma unroll
    for (int i = 0; i < 4; i++) bias[i] = __ldg(&b2[j0 + 32 * i]);

    for (int tile = blockIdx.x; tile < NN / 64; tile += gridDim.x) {
        int row0 = tile * 64;
        __syncthreads();
        #pragma unroll
        for (int i = 0; i < 16; i++) {
            int idx = t + i * 256;          // 4096 quads = 64 rows * 64 quads
            int r = idx >> 6, kq = idx & 63;
            float4 v;
            if (kq < 32) {
                float inv = 1.0f / fmaxf(g_cnt[row0 + r], 1.0f);
                v = *(const float4*)(g_agg2 + (size_t)(row0 + r) * HH + kq * 4);
                v.x *= inv; v.y *= inv; v.z *= inv; v.w *= inv;
            } else {
                v = *(const float4*)(g_h1 + (size_t)(row0 + r) * HH + (kq - 32) * 4);
            }
            *(float4*)(sIn + r * 256 + kq * 4) = v;
        }
        __syncthreads();
        float acc[8][4];
        #pragma unroll
        for (int r = 0; r < 8; r++)
            #pragma unroll
            for (int i = 0; i < 4; i++) acc[r][i] = bias[i];
        #pragma unroll 4
        for (int k = 0; k < 256; k++) {
            float w0 = sW[k * 129 + j0];
            float w1 = sW[k * 129 + j0 + 32];
            float w2 = sW[k * 129 + j0 + 64];
            float w3 = sW[k * 129 + j0 + 96];
            #pragma unroll
            for (int r = 0; r < 8; r++) {
                float a = sIn[(r0 + r) * 256 + k];
                acc[r][0] += a * w0; acc[r][1] += a * w1;
                acc[r][2] += a * w2; acc[r][3] += a * w3;
            }
        }
        #pragma unroll
        for (int r = 0; r < 8; r++)
            #pragma unroll
            for (int i = 0; i < 4; i++)
                g_nemb[(size_t)(row0 + r0 + r) * HH + j0 + 32 * i] = fmaxf(acc[r][i], 0.0f);
    }
}

// ---------------- graph mean pooling (batch is sorted; segmented flush) ------
__global__ void pool_kernel(const int* __restrict__ batch) {
    int j = threadIdx.x;                  // 128
    int n0 = blockIdx.x * 256;
    float sum = 0.0f, cc = 0.0f;
    int cur = __ldg(&batch[n0]);
    for (int r = 0; r < 256; r++) {
        int b = __ldg(&batch[n0 + r]);
        if (b != cur) {
            atomicAdd(&g_gsum[cur * HH + j], sum);
            if (j == 0) atomicAdd(&g_gcnt[cur], cc);
            sum = 0.0f; cc = 0.0f; cur = b;
        }
        sum += g_nemb[(size_t)(n0 + r) * HH + j];
        cc += 1.0f;
    }
    atomicAdd(&g_gsum[cur * HH + j], sum);
    if (j == 0) atomicAdd(&g_gcnt[cur], cc);
}

// ---------------- Whh transpose ---------------------------------------------
__global__ void transpose_whh(const float* __restrict__ Whh) {
    int idx = blockIdx.x * 256 + threadIdx.x;   // 65536
    int j = idx >> 7, k = idx & 127;
    g_WT[k * 512 + j] = Whh[idx];
}

// ---------------- LSTM input GEMM: Xg = nemb[path_idx] @ Wih^T + bih + bhh ---
__global__ void xg_gemm_kernel(const int* __restrict__ path_idx, const float* __restrict__ Wih,
                               const float* __restrict__ bih, const float* __restrict__ bhh) {
    extern __shared__ float sm[];
    float* sW = sm;                 // [128][129]
    float* sIn = sm + 128 * 129;    // [64][128]
    __shared__ int snode[64];
    int t = threadIdx.x;
    int jbase = blockIdx.y * 128;
    #pragma unroll 4
    for (int i = 0; i < 64; i++) {
        int idx = t + i * 256;
        int j = idx >> 7, k = idx & 127;
        sW[k * 129 + j] = Wih[(size_t)(jbase + j) * 128 + k];
    }
    int j0 = t & 31, r0 = (t >> 5) * 8;
    float bias[4];
    #pragma unroll
    for (int i = 0; i < 4; i++)
        bias[i] = __ldg(&bih[jbase + j0 + 32 * i]) + __ldg(&bhh[jbase + j0 + 32 * i]);
    int row0 = blockIdx.x * 64;
    if (t < 64) snode[t] = path_idx[row0 + t];
    __syncthreads();
    #pragma unroll
    for (int i = 0; i < 8; i++) {
        int idx = t + i * 256;              // 2048 quads = 64 rows * 32 quads
        int r = idx >> 5, kq = idx & 31;
        int node = snode[r];
        float4 v = *(const float4*)(g_nemb + (size_t)node * HH + kq * 4);
        *(float4*)(sIn + r * 128 + kq * 4) = v;
    }
    __syncthreads();
    float acc[8][4];
    #pragma unroll
    for (int r = 0; r < 8; r++)
        #pragma unroll
        for (int i = 0; i < 4; i++) acc[r][i] = bias[i];
    #pragma unroll 4
    for (int k = 0; k < 128; k++) {
        float w0 = sW[k * 129 + j0];
        float w1 = sW[k * 129 + j0 + 32];
        float w2 = sW[k * 129 + j0 + 64];
        float w3 = sW[k * 129 + j0 + 96];
        #pragma unroll
        for (int r = 0; r < 8; r++) {
            float a = sIn[(r0 + r) * 128 + k];
            acc[r][0] += a * w0; acc[r][1] += a * w1;
            acc[r][2] += a * w2; acc[r][3] += a * w3;
        }
    }
    #pragma unroll
    for (int r = 0; r < 8; r++)
        #pragma unroll
        for (int i = 0; i < 4; i++)
            g_Xg[(size_t)(row0 + r0 + r) * 512 + jbase + j0 + 32 * i] = acc[r][i];
}

// ---------------- LSTM recurrence: 64 blocks x 4 batch rows, h/c in smem -----
__global__ void lstm_kernel(const int* __restrict__ path_len) {
    __shared__ float sh[4 * 128];
    __shared__ float scm[4 * 128];
    __shared__ float sG[4 * 512];
    __shared__ int splen[4];
    int t = threadIdx.x;                  // 256
    int b0 = blockIdx.x * 4;
    for (int i = t; i < 512; i += 256) { sh[i] = 0.0f; scm[i] = 0.0f; }
    if (t < 4) splen[t] = path_len[b0 + t];
    __syncthreads();
    int half = t >> 7;                    // 0..1 -> batches {2*half, 2*half+1}
    int jq = t & 127;                     // gate-col quad base
    int bA = half * 2, bB = half * 2 + 1;
    for (int step = 0; step < LL; step++) {
        float4 a0 = *(const float4*)(g_Xg + ((size_t)(b0 + bA) * LL + step) * 512 + jq * 4);
        float4 a1 = *(const float4*)(g_Xg + ((size_t)(b0 + bB) * LL + step) * 512 + jq * 4);
        #pragma unroll 4
        for (int k = 0; k < 128; k++) {
            float4 w = *(const float4*)(g_WT + k * 512 + jq * 4);
            float hA = sh[bA * 128 + k];
            float hB = sh[bB * 128 + k];
            a0.x += w.x * hA; a0.y += w.y * hA; a0.z += w.z * hA; a0.w += w.w * hA;
            a1.x += w.x * hB; a1.y += w.y * hB; a1.z += w.z * hB; a1.w += w.w * hB;
        }
        *(float4*)(sG + bA * 512 + jq * 4) = a0;
        *(float4*)(sG + bB * 512 + jq * 4) = a1;
        __syncthreads();
        #pragma unroll
        for (int u = 0; u < 2; u++) {
            int idx = t + u * 256;
            int b = idx >> 7, j = idx & 127;
            float ig = sG[b * 512 + j];
            float fg = sG[b * 512 + 128 + j];
            float gg = sG[b * 512 + 256 + j];
            float og = sG[b * 512 + 384 + j];
            float cn = sigf(fg) * scm[b * 128 + j] + sigf(ig) * tanhf(gg);
            float hn = sigf(og) * tanhf(cn);
            if (step < splen[b]) { scm[b * 128 + j] = cn; sh[b * 128 + j] = hn; }
        }
        __syncthreads();
    }
    for (int i = t; i < 512; i += 256) g_pemb[b0 * 128 + i] = sh[i];
}

// ---------------- scoring head ----------------------------------------------
__global__ void head_kernel(const float* __restrict__ flow, const float* __restrict__ Wf,
                            const float* __restrict__ bf, const float* __restrict__ Ws1,
                            const float* __restrict__ bs1, const float* __restrict__ Ws2,
                            const float* __restrict__ bs2, float* __restrict__ out) {
    __shared__ float comb[320];
    __shared__ float red_[128];
    int b = blockIdx.x, j = threadIdx.x;  // 128 threads
    comb[j] = g_gsum[b * HH + j] * (1.0f / fmaxf(g_gcnt[b], 1.0f));
    comb[128 + j] = g_pemb[b * HH + j];
    if (j < 64) {
        float a = __ldg(&bf[j]);
        #pragma unroll
        for (int k = 0; k < FF; k++) a += flow[b * FF + k] * Wf[j * FF + k];
        comb[256 + j] = fmaxf(a, 0.0f);
    }
    __syncthreads();
    float acc = __ldg(&bs1[j]);
    const float4* wr = (const float4*)(Ws1 + (size_t)j * 320);
    const float4* cb = (const float4*)comb;
    #pragma unroll 8
    for (int k = 0; k < 80; k++) {
        float4 w = wr[k], c = cb[k];
        acc += w.x * c.x + w.y * c.y + w.z * c.z + w.w * c.w;
    }
    float h = fmaxf(acc, 0.0f);
    red_[j] = h * __ldg(&Ws2[j]);
    __syncthreads();
    for (int s = 64; s > 0; s >>= 1) {
        if (j < s) red_[j] += red_[j + s];
        __syncthreads();
    }
    if (j == 0) out[b] = red_[0] + __ldg(&bs2[0]);
}

// ---------------- launch ----------------------------------------------------
extern "C" void kernel_launch(void* const* d_in, const int* in_sizes, int n_in,
                              void* d_out, int out_size) {
    const float* x        = (const float*)d_in[0];
    const int*   ei       = (const int*)d_in[1];
    const int*   batch    = (const int*)d_in[2];
    const int*   path_idx = (const int*)d_in[3];
    const int*   path_len = (const int*)d_in[4];
    const float* flow     = (const float*)d_in[5];
    const float* Wl1 = (const float*)d_in[6];
    const float* Wr1 = (const float*)d_in[7];
    const float* b1  = (const float*)d_in[8];
    const float* Wl2 = (const float*)d_in[9];
    const float* Wr2 = (const float*)d_in[10];
    const float* b2  = (const float*)d_in[11];
    const float* Wih = (const float*)d_in[12];
    const float* Whh = (const float*)d_in[13];
    const float* bih = (const float*)d_in[14];
    const float* bhh = (const float*)d_in[15];
    const float* Wf  = (const float*)d_in[16];
    const float* bf  = (const float*)d_in[17];
    const float* Ws1 = (const float*)d_in[18];
    const float* bs1 = (const float*)d_in[19];
    const float* Ws2 = (const float*)d_in[20];
    const float* bs2 = (const float*)d_in[21];
    float* out = (float*)d_out;

    const int SM1 = (128 * 129 + 64 * 128) * 4;   // 98816 B
    const int SM2 = (256 * 129 + 64 * 256) * 4;   // 197632 B
    cudaFuncSetAttribute(gemm1_kernel,   cudaFuncAttributeMaxDynamicSharedMemorySize, SM1);
    cudaFuncSetAttribute(gemm2_kernel,   cudaFuncAttributeMaxDynamicSharedMemorySize, SM2);
    cudaFuncSetAttribute(xg_gemm_kernel, cudaFuncAttributeMaxDynamicSharedMemorySize, SM1);

    zero_scratch<<<65536, 256>>>();
    scatter1_kernel<<<131072, 256>>>(ei, x);
    gemm1_kernel<<<512, 256, SM1>>>(x, Wl1, Wr1, b1);
    scatter2_kernel<<<262144, 256>>>(ei);
    gemm2_kernel<<<512, 256, SM2>>>(Wl2, Wr2, b2);
    pool_kernel<<<512, 128>>>(batch);
    transpose_whh<<<256, 256>>>(Whh);
    xg_gemm_kernel<<<dim3(128, 4), 256, SM1>>>(path_idx, Wih, bih, bhh);
    lstm_kernel<<<64, 256>>>(path_len);
    head_kernel<<<256, 128>>>(flow, Wf, bf, Ws1, bs1, Ws2, bs2, out);
}

// round 2
// speedup vs baseline: 1.5117x; 1.5117x over previous
#include <cuda_runtime.h>
#include <cuda_bf16.h>
#include <math.h>

#define NN 131072
#define FN 64
#define FF 16
#define HH 128
#define EE 2097152
#define BB 256
#define LL 32
#define NTILES (NN / 64)

// ---------------- scratch (device globals; no allocations allowed) ----------
__device__ int   g_deg[NN];
__device__ int   g_rowptr[NN + 1];
__device__ int   g_cursor[NN];
__device__ int   g_esrc[EE];
__device__ int   g_blksum[512];
__device__ float g_inv[NN];

__device__ float g_agg1[NN * FN];      // mean of neighbors (layer 1 input agg)
__device__ float g_h1[NN * HH];
__device__ float g_agg2[NN * HH];
__device__ float g_nemb[NN * HH];
__device__ float g_gsum[BB * HH];
__device__ float g_gcnt[BB];
__device__ float g_Xg[BB * LL * 4 * HH];
__device__ float g_WT[HH * 4 * HH];
__device__ float g_pemb[BB * HH];

__device__ __forceinline__ float sigf(float x) { return 1.0f / (1.0f + __expf(-x)); }

// ---------------- CSR build --------------------------------------------------
__global__ void zero_small() {
    int i = blockIdx.x * 256 + threadIdx.x;      // 131072 threads
    g_deg[i] = 0;
    if (i < BB * HH) g_gsum[i] = 0.0f;
    if (i < BB)      g_gcnt[i] = 0.0f;
    if (i == 0)      g_rowptr[NN] = EE;
}

__global__ void count_kernel(const int* __restrict__ ei) {
    int e = blockIdx.x * 256 + threadIdx.x;      // EE threads
    atomicAdd(&g_deg[__ldg(&ei[EE + e])], 1);
}

__global__ void blocksum_kernel() {
    __shared__ int s[256];
    int t = threadIdx.x;
    s[t] = g_deg[blockIdx.x * 256 + t];
    __syncthreads();
    for (int off = 128; off > 0; off >>= 1) {
        if (t < off) s[t] += s[t + off];
        __syncthreads();
    }
    if (t == 0) g_blksum[blockIdx.x] = s[0];
}

__global__ void scan512_kernel() {
    __shared__ int s[512];
    int t = threadIdx.x;
    int v = g_blksum[t];
    s[t] = v;
    __syncthreads();
    for (int off = 1; off < 512; off <<= 1) {
        int u = (t >= off) ? s[t - off] : 0;
        __syncthreads();
        s[t] += u;
        __syncthreads();
    }
    g_blksum[t] = s[t] - v;   // exclusive
}

__global__ void rowptr_kernel() {
    __shared__ int s[256];
    int t = threadIdx.x;
    int i = blockIdx.x * 256 + t;
    int d = g_deg[i];
    s[t] = d;
    __syncthreads();
    for (int off = 1; off < 256; off <<= 1) {
        int u = (t >= off) ? s[t - off] : 0;
        __syncthreads();
        s[t] += u;
        __syncthreads();
    }
    int excl = g_blksum[blockIdx.x] + s[t] - d;
    g_rowptr[i] = excl;
    g_cursor[i] = excl;
    g_inv[i] = 1.0f / fmaxf((float)d, 1.0f);
}

__global__ void escatter_kernel(const int* __restrict__ ei) {
    int e = blockIdx.x * 256 + threadIdx.x;      // EE threads
    int src = __ldg(&ei[e]);
    int dst = __ldg(&ei[EE + e]);
    int pos = atomicAdd(&g_cursor[dst], 1);
    g_esrc[pos] = src;
}

// ---------------- aggregation (warp per node, register accumulation) --------
__global__ void agg1_kernel(const float* __restrict__ x) {
    int warp = threadIdx.x >> 5, lane = threadIdx.x & 31;
    int n = blockIdx.x * 8 + warp;
    int beg = g_rowptr[n], end = g_rowptr[n + 1];
    float2 acc = make_float2(0.0f, 0.0f);
    int i = beg;
    for (; i + 1 < end; i += 2) {
        int s0 = __ldg(&g_esrc[i]);
        int s1 = __ldg(&g_esrc[i + 1]);
        float2 v0 = *(const float2*)(x + (size_t)s0 * FN + lane * 2);
        float2 v1 = *(const float2*)(x + (size_t)s1 * FN + lane * 2);
        acc.x += v0.x + v1.x;
        acc.y += v0.y + v1.y;
    }
    if (i < end) {
        int s0 = __ldg(&g_esrc[i]);
        float2 v0 = *(const float2*)(x + (size_t)s0 * FN + lane * 2);
        acc.x += v0.x; acc.y += v0.y;
    }
    float inv = g_inv[n];
    *(float2*)(g_agg1 + (size_t)n * FN + lane * 2) = make_float2(acc.x * inv, acc.y * inv);
}

__global__ void agg2_kernel() {
    int warp = threadIdx.x >> 5, lane = threadIdx.x & 31;
    int n = blockIdx.x * 8 + warp;
    int beg = g_rowptr[n], end = g_rowptr[n + 1];
    float4 acc = make_float4(0.0f, 0.0f, 0.0f, 0.0f);
    int i = beg;
    for (; i + 1 < end; i += 2) {
        int s0 = __ldg(&g_esrc[i]);
        int s1 = __ldg(&g_esrc[i + 1]);
        float4 v0 = *(const float4*)(g_h1 + (size_t)s0 * HH + lane * 4);
        float4 v1 = *(const float4*)(g_h1 + (size_t)s1 * HH + lane * 4);
        acc.x += v0.x + v1.x; acc.y += v0.y + v1.y;
        acc.z += v0.z + v1.z; acc.w += v0.w + v1.w;
    }
    if (i < end) {
        int s0 = __ldg(&g_esrc[i]);
        float4 v0 = *(const float4*)(g_h1 + (size_t)s0 * HH + lane * 4);
        acc.x += v0.x; acc.y += v0.y; acc.z += v0.z; acc.w += v0.w;
    }
    float inv = g_inv[n];
    acc.x *= inv; acc.y *= inv; acc.z *= inv; acc.w *= inv;
    *(float4*)(g_agg2 + (size_t)n * HH + lane * 4) = acc;
}

// ---------------- GEMM core: 64x128 tile, thread = 8 rows x 4 consecutive cols
// sW layout: [K][132] (padded), sIn: [64][K] row-major.
template<int K>
__device__ __forceinline__ void mma_tile(const float* __restrict__ sW,
                                         const float* __restrict__ sIn,
                                         float4 acc[8], int j4, int r0) {
    #pragma unroll 2
    for (int k = 0; k < K; k += 4) {
        float4 w0 = *(const float4*)(sW + (k + 0) * 132 + j4 * 4);
        float4 w1 = *(const float4*)(sW + (k + 1) * 132 + j4 * 4);
        float4 w2 = *(const float4*)(sW + (k + 2) * 132 + j4 * 4);
        float4 w3 = *(const float4*)(sW + (k + 3) * 132 + j4 * 4);
        #pragma unroll
        for (int r = 0; r < 8; r++) {
            float4 a = *(const float4*)(sIn + (r0 + r) * K + k);
            acc[r].x += a.x * w0.x; acc[r].y += a.x * w0.y; acc[r].z += a.x * w0.z; acc[r].w += a.x * w0.w;
            acc[r].x += a.y * w1.x; acc[r].y += a.y * w1.y; acc[r].z += a.y * w1.z; acc[r].w += a.y * w1.w;
            acc[r].x += a.z * w2.x; acc[r].y += a.z * w2.y; acc[r].z += a.z * w2.z; acc[r].w += a.z * w2.w;
            acc[r].x += a.w * w3.x; acc[r].y += a.w * w3.y; acc[r].z += a.w * w3.z; acc[r].w += a.w * w3.w;
        }
    }
}

// ---------------- SAGE layer 1: h1 = relu([mean1|x] @ [Wl1;Wr1]^T + b1) -----
__global__ void gemm1_kernel(const float* __restrict__ x, const float* __restrict__ Wl,
                             const float* __restrict__ Wr, const float* __restrict__ b1) {
    extern __shared__ float sm[];
    float* sW = sm;                   // [128][132]
    float* sIn = sm + 128 * 132;      // [64][128]
    int t = threadIdx.x;
    #pragma unroll 4
    for (int i = 0; i < 64; i++) {
        int idx = t + i * 256;
        int j = idx >> 7, k = idx & 127;
        float v = (k < 64) ? __ldg(&Wl[j * 64 + k]) : __ldg(&Wr[j * 64 + (k - 64)]);
        sW[k * 132 + j] = v;
    }
    int j4 = t & 31, r0 = (t >> 5) * 8;
    float4 bias = *(const float4*)(b1 + j4 * 4);

    for (int tile = blockIdx.x; tile < NTILES; tile += gridDim.x) {
        int row0 = tile * 64;
        __syncthreads();
        #pragma unroll
        for (int i = 0; i < 8; i++) {
            int idx = t + i * 256;        // 2048 quads = 64 rows * 32 quads
            int r = idx >> 5, kq = idx & 31;
            float4 v;
            if (kq < 16) v = *(const float4*)(g_agg1 + (size_t)(row0 + r) * FN + kq * 4);
            else         v = *(const float4*)(x + (size_t)(row0 + r) * FN + (kq - 16) * 4);
            *(float4*)(sIn + r * 128 + kq * 4) = v;
        }
        __syncthreads();
        float4 acc[8];
        #pragma unroll
        for (int r = 0; r < 8; r++) acc[r] = bias;
        mma_tile<128>(sW, sIn, acc, j4, r0);
        #pragma unroll
        for (int r = 0; r < 8; r++) {
            float4 o = acc[r];
            o.x = fmaxf(o.x, 0.0f); o.y = fmaxf(o.y, 0.0f);
            o.z = fmaxf(o.z, 0.0f); o.w = fmaxf(o.w, 0.0f);
            *(float4*)(g_h1 + (size_t)(row0 + r0 + r) * HH + j4 * 4) = o;
        }
    }
}

// ---------------- SAGE layer 2: nemb = relu([mean2|h1] @ [Wl2;Wr2]^T + b2) --
__global__ void gemm2_kernel(const float* __restrict__ Wl, const float* __restrict__ Wr,
                             const float* __restrict__ b2) {
    extern __shared__ float sm[];
    float* sW = sm;                   // [256][132]
    float* sIn = sm + 256 * 132;      // [64][256]
    int t = threadIdx.x;
    #pragma unroll 4
    for (int i = 0; i < 128; i++) {
        int idx = t + i * 256;
        int j = idx >> 8, k = idx & 255;
        float v = (k < 128) ? __ldg(&Wl[j * 128 + k]) : __ldg(&Wr[j * 128 + (k - 128)]);
        sW[k * 132 + j] = v;
    }
    int j4 = t & 31, r0 = (t >> 5) * 8;
    float4 bias = *(const float4*)(b2 + j4 * 4);

    for (int tile = blockIdx.x; tile < NTILES; tile += gridDim.x) {
        int row0 = tile * 64;
        __syncthreads();
        #pragma unroll
        for (int i = 0; i < 16; i++) {
            int idx = t + i * 256;        // 4096 quads = 64 rows * 64 quads
            int r = idx >> 6, kq = idx & 63;
            float4 v;
            if (kq < 32) v = *(const float4*)(g_agg2 + (size_t)(row0 + r) * HH + kq * 4);
            else         v = *(const float4*)(g_h1 + (size_t)(row0 + r) * HH + (kq - 32) * 4);
            *(float4*)(sIn + r * 256 + kq * 4) = v;
        }
        __syncthreads();
        float4 acc[8];
        #pragma unroll
        for (int r = 0; r < 8; r++) acc[r] = bias;
        mma_tile<256>(sW, sIn, acc, j4, r0);
        #pragma unroll
        for (int r = 0; r < 8; r++) {
            float4 o = acc[r];
            o.x = fmaxf(o.x, 0.0f); o.y = fmaxf(o.y, 0.0f);
            o.z = fmaxf(o.z, 0.0f); o.w = fmaxf(o.w, 0.0f);
            *(float4*)(g_nemb + (size_t)(row0 + r0 + r) * HH + j4 * 4) = o;
        }
    }
}

// ---------------- graph mean pooling (batch sorted; segmented flush) ---------
__global__ void pool_kernel(const int* __restrict__ batch) {
    int j = threadIdx.x;                  // 128
    int n0 = blockIdx.x * 256;
    float sum = 0.0f, cc = 0.0f;
    int cur = __ldg(&batch[n0]);
    for (int r = 0; r < 256; r++) {
        int b = __ldg(&batch[n0 + r]);
        if (b != cur) {
            atomicAdd(&g_gsum[cur * HH + j], sum);
            if (j == 0) atomicAdd(&g_gcnt[cur], cc);
            sum = 0.0f; cc = 0.0f; cur = b;
        }
        sum += g_nemb[(size_t)(n0 + r) * HH + j];
        cc += 1.0f;
    }
    atomicAdd(&g_gsum[cur * HH + j], sum);
    if (j == 0) atomicAdd(&g_gcnt[cur], cc);
}

// ---------------- Whh transpose ---------------------------------------------
__global__ void transpose_whh(const float* __restrict__ Whh) {
    int idx = blockIdx.x * 256 + threadIdx.x;   // 65536
    int j = idx >> 7, k = idx & 127;
    g_WT[k * 512 + j] = Whh[idx];
}

// ---------------- LSTM input GEMM: Xg = nemb[path_idx] @ Wih^T + bih + bhh ---
__global__ void xg_gemm_kernel(const int* __restrict__ path_idx, const float* __restrict__ Wih,
                               const float* __restrict__ bih, const float* __restrict__ bhh) {
    extern __shared__ float sm[];
    float* sW = sm;                   // [128][132]
    float* sIn = sm + 128 * 132;      // [64][128]
    __shared__ int snode[64];
    int t = threadIdx.x;
    int jbase = blockIdx.y * 128;
    #pragma unroll 4
    for (int i = 0; i < 64; i++) {
        int idx = t + i * 256;
        int j = idx >> 7, k = idx & 127;
        sW[k * 132 + j] = __ldg(&Wih[(size_t)(jbase + j) * 128 + k]);
    }
    int j4 = t & 31, r0 = (t >> 5) * 8;
    float4 bias;
    {
        float4 a = *(const float4*)(bih + jbase + j4 * 4);
        float4 b = *(const float4*)(bhh + jbase + j4 * 4);
        bias = make_float4(a.x + b.x, a.y + b.y, a.z + b.z, a.w + b.w);
    }
    int row0 = blockIdx.x * 64;
    if (t < 64) snode[t] = __ldg(&path_idx[row0 + t]);
    __syncthreads();
    #pragma unroll
    for (int i = 0; i < 8; i++) {
        int idx = t + i * 256;            // 2048 quads
        int r = idx >> 5, kq = idx & 31;
        int node = snode[r];
        float4 v = *(const float4*)(g_nemb + (size_t)node * HH + kq * 4);
        *(float4*)(sIn + r * 128 + kq * 4) = v;
    }
    __syncthreads();
    float4 acc[8];
    #pragma unroll
    for (int r = 0; r < 8; r++) acc[r] = bias;
    mma_tile<128>(sW, sIn, acc, j4, r0);
    #pragma unroll
    for (int r = 0; r < 8; r++)
        *(float4*)(g_Xg + (size_t)(row0 + r0 + r) * 512 + jbase + j4 * 4) = acc[r];
}

// ---------------- LSTM recurrence: 64 blocks x 4 batch rows, h/c in smem -----
__global__ void lstm_kernel(const int* __restrict__ path_len) {
    __shared__ float sh[4 * 128];
    __shared__ float scm[4 * 128];
    __shared__ float sG[4 * 512];
    __shared__ int splen[4];
    int t = threadIdx.x;                  // 256
    int b0 = blockIdx.x * 4;
    for (int i = t; i < 512; i += 256) { sh[i] = 0.0f; scm[i] = 0.0f; }
    if (t < 4) splen[t] = path_len[b0 + t];
    __syncthreads();
    int half = t >> 7;
    int jq = t & 127;
    int bA = half * 2, bB = half * 2 + 1;
    for (int step = 0; step < LL; step++) {
        float4 a0 = *(const float4*)(g_Xg + ((size_t)(b0 + bA) * LL + step) * 512 + jq * 4);
        float4 a1 = *(const float4*)(g_Xg + ((size_t)(b0 + bB) * LL + step) * 512 + jq * 4);
        #pragma unroll 4
        for (int k = 0; k < 128; k++) {
            float4 w = *(const float4*)(g_WT + k * 512 + jq * 4);
            float hA = sh[bA * 128 + k];
            float hB = sh[bB * 128 + k];
            a0.x += w.x * hA; a0.y += w.y * hA; a0.z += w.z * hA; a0.w += w.w * hA;
            a1.x += w.x * hB; a1.y += w.y * hB; a1.z += w.z * hB; a1.w += w.w * hB;
        }
        *(float4*)(sG + bA * 512 + jq * 4) = a0;
        *(float4*)(sG + bB * 512 + jq * 4) = a1;
        __syncthreads();
        #pragma unroll
        for (int u = 0; u < 2; u++) {
            int idx = t + u * 256;
            int b = idx >> 7, j = idx & 127;
            float ig = sG[b * 512 + j];
            float fg = sG[b * 512 + 128 + j];
            float gg = sG[b * 512 + 256 + j];
            float og = sG[b * 512 + 384 + j];
            float cn = sigf(fg) * scm[b * 128 + j] + sigf(ig) * tanhf(gg);
            float hn = sigf(og) * tanhf(cn);
            if (step < splen[b]) { scm[b * 128 + j] = cn; sh[b * 128 + j] = hn; }
        }
        __syncthreads();
    }
    for (int i = t; i < 512; i += 256) g_pemb[b0 * 128 + i] = sh[i];
}

// ---------------- scoring head ----------------------------------------------
__global__ void head_kernel(const float* __restrict__ flow, const float* __restrict__ Wf,
                            const float* __restrict__ bf, const float* __restrict__ Ws1,
                            const float* __restrict__ bs1, const float* __restrict__ Ws2,
                            const float* __restrict__ bs2, float* __restrict__ out) {
    __shared__ float comb[320];
    __shared__ float red_[128];
    int b = blockIdx.x, j = threadIdx.x;  // 128 threads
    comb[j] = g_gsum[b * HH + j] * (1.0f / fmaxf(g_gcnt[b], 1.0f));
    comb[128 + j] = g_pemb[b * HH + j];
    if (j < 64) {
        float a = __ldg(&bf[j]);
        #pragma unroll
        for (int k = 0; k < FF; k++) a += flow[b * FF + k] * Wf[j * FF + k];
        comb[256 + j] = fmaxf(a, 0.0f);
    }
    __syncthreads();
    float acc = __ldg(&bs1[j]);
    const float4* wr = (const float4*)(Ws1 + (size_t)j * 320);
    const float4* cb = (const float4*)comb;
    #pragma unroll 8
    for (int k = 0; k < 80; k++) {
        float4 w = wr[k], c = cb[k];
        acc += w.x * c.x + w.y * c.y + w.z * c.z + w.w * c.w;
    }
    float h = fmaxf(acc, 0.0f);
    red_[j] = h * __ldg(&Ws2[j]);
    __syncthreads();
    for (int s = 64; s > 0; s >>= 1) {
        if (j < s) red_[j] += red_[j + s];
        __syncthreads();
    }
    if (j == 0) out[b] = red_[0] + __ldg(&bs2[0]);
}

// ---------------- launch ----------------------------------------------------
extern "C" void kernel_launch(void* const* d_in, const int* in_sizes, int n_in,
                              void* d_out, int out_size) {
    const float* x        = (const float*)d_in[0];
    const int*   ei       = (const int*)d_in[1];
    const int*   batch    = (const int*)d_in[2];
    const int*   path_idx = (const int*)d_in[3];
    const int*   path_len = (const int*)d_in[4];
    const float* flow     = (const float*)d_in[5];
    const float* Wl1 = (const float*)d_in[6];
    const float* Wr1 = (const float*)d_in[7];
    const float* b1  = (const float*)d_in[8];
    const float* Wl2 = (const float*)d_in[9];
    const float* Wr2 = (const float*)d_in[10];
    const float* b2  = (const float*)d_in[11];
    const float* Wih = (const float*)d_in[12];
    const float* Whh = (const float*)d_in[13];
    const float* bih = (const float*)d_in[14];
    const float* bhh = (const float*)d_in[15];
    const float* Wf  = (const float*)d_in[16];
    const float* bf  = (const float*)d_in[17];
    const float* Ws1 = (const float*)d_in[18];
    const float* bs1 = (const float*)d_in[19];
    const float* Ws2 = (const float*)d_in[20];
    const float* bs2 = (const float*)d_in[21];
    float* out = (float*)d_out;

    const int SM1 = (128 * 132 + 64 * 128) * 4;   // 100352 B
    const int SM2 = (256 * 132 + 64 * 256) * 4;   // 200704 B
    cudaFuncSetAttribute(gemm1_kernel,   cudaFuncAttributeMaxDynamicSharedMemorySize, SM1);
    cudaFuncSetAttribute(gemm2_kernel,   cudaFuncAttributeMaxDynamicSharedMemorySize, SM2);
    cudaFuncSetAttribute(xg_gemm_kernel, cudaFuncAttributeMaxDynamicSharedMemorySize, SM1);

    zero_small<<<512, 256>>>();
    count_kernel<<<8192, 256>>>(ei);
    blocksum_kernel<<<512, 256>>>();
    scan512_kernel<<<1, 512>>>();
    rowptr_kernel<<<512, 256>>>();
    escatter_kernel<<<8192, 256>>>(ei);
    agg1_kernel<<<16384, 256>>>(x);
    gemm1_kernel<<<296, 256, SM1>>>(x, Wl1, Wr1, b1);
    agg2_kernel<<<16384, 256>>>();
    gemm2_kernel<<<148, 256, SM2>>>(Wl2, Wr2, b2);
    pool_kernel<<<512, 128>>>(batch);
    transpose_whh<<<256, 256>>>(Whh);
    xg_gemm_kernel<<<dim3(128, 4), 256, SM1>>>(path_idx, Wih, bih, bhh);
    lstm_kernel<<<64, 256>>>(path_len);
    head_kernel<<<256, 128>>>(flow, Wf, bf, Ws1, bs1, Ws2, bs2, out);
}

// round 4
// speedup vs baseline: 1.8296x; 1.2103x over previous
#include <cuda_runtime.h>
#include <cuda_bf16.h>
#include <math.h>
#include <stdint.h>

#define NN 131072
#define FN 64
#define FF 16
#define HH 128
#define EE 2097152
#define BB 256
#define LL 32

// ---------------- scratch (device globals; no allocations allowed) ----------
__device__ int   g_deg[NN];
__device__ int   g_rowptr[NN + 1];
__device__ int   g_cursor[NN];
__device__ int   g_esrc[EE];
__device__ int   g_blksum[512];
__device__ float g_inv[NN];

__device__ float g_agg1[NN * FN];
__device__ float g_h1[NN * HH];
__device__ float g_agg2[NN * HH];
__device__ float g_nemb[NN * HH];
__device__ float g_gsum[BB * HH];
__device__ float g_gcnt[BB];
__device__ float g_Xg[BB * LL * 4 * HH];
__device__ float g_WT[HH * 4 * HH];
__device__ float g_pemb[BB * HH];

__device__ __forceinline__ float sigf(float x) { return 1.0f / (1.0f + __expf(-x)); }

__device__ __forceinline__ uint32_t cvt_tf32(float f) {
    uint32_t r; asm("cvt.rna.tf32.f32 %0, %1;" : "=r"(r) : "f"(f)); return r;
}
__device__ __forceinline__ void mma_tf32(float4& c, const uint32_t a[4], uint32_t b0, uint32_t b1) {
    asm volatile("mma.sync.aligned.m16n8k8.row.col.f32.tf32.tf32.f32 "
                 "{%0,%1,%2,%3}, {%4,%5,%6,%7}, {%8,%9}, {%0,%1,%2,%3};"
                 : "+f"(c.x), "+f"(c.y), "+f"(c.z), "+f"(c.w)
                 : "r"(a[0]), "r"(a[1]), "r"(a[2]), "r"(a[3]), "r"(b0), "r"(b1));
}

// ---------------- CSR build --------------------------------------------------
__global__ void zero_small() {
    int i = blockIdx.x * 256 + threadIdx.x;
    g_deg[i] = 0;
    if (i < BB * HH) g_gsum[i] = 0.0f;
    if (i < BB)      g_gcnt[i] = 0.0f;
    if (i == 0)      g_rowptr[NN] = EE;
}

__global__ void count_kernel(const int* __restrict__ ei) {
    int e = blockIdx.x * 256 + threadIdx.x;
    atomicAdd(&g_deg[__ldg(&ei[EE + e])], 1);
}

__global__ void blocksum_kernel() {
    __shared__ int s[256];
    int t = threadIdx.x;
    s[t] = g_deg[blockIdx.x * 256 + t];
    __syncthreads();
    for (int off = 128; off > 0; off >>= 1) {
        if (t < off) s[t] += s[t + off];
        __syncthreads();
    }
    if (t == 0) g_blksum[blockIdx.x] = s[0];
}

__global__ void scan512_kernel() {
    __shared__ int s[512];
    int t = threadIdx.x;
    int v = g_blksum[t];
    s[t] = v;
    __syncthreads();
    for (int off = 1; off < 512; off <<= 1) {
        int u = (t >= off) ? s[t - off] : 0;
        __syncthreads();
        s[t] += u;
        __syncthreads();
    }
    g_blksum[t] = s[t] - v;
}

__global__ void rowptr_kernel() {
    __shared__ int s[256];
    int t = threadIdx.x;
    int i = blockIdx.x * 256 + t;
    int d = g_deg[i];
    s[t] = d;
    __syncthreads();
    for (int off = 1; off < 256; off <<= 1) {
        int u = (t >= off) ? s[t - off] : 0;
        __syncthreads();
        s[t] += u;
        __syncthreads();
    }
    int excl = g_blksum[blockIdx.x] + s[t] - d;
    g_rowptr[i] = excl;
    g_cursor[i] = excl;
    g_inv[i] = 1.0f / fmaxf((float)d, 1.0f);
}

__global__ void escatter_kernel(const int* __restrict__ ei) {
    int e = blockIdx.x * 256 + threadIdx.x;
    int src = __ldg(&ei[e]);
    int dst = __ldg(&ei[EE + e]);
    int pos = atomicAdd(&g_cursor[dst], 1);
    g_esrc[pos] = src;
}

// ---------------- aggregation -------------------------------------------------
__global__ void agg1_kernel(const float* __restrict__ x) {
    int warp = threadIdx.x >> 5, lane = threadIdx.x & 31;
    int n = blockIdx.x * 8 + warp;
    int beg = g_rowptr[n], end = g_rowptr[n + 1];
    float2 acc = make_float2(0.0f, 0.0f);
    int i = beg;
    for (; i + 1 < end; i += 2) {
        int s0 = __ldg(&g_esrc[i]);
        int s1 = __ldg(&g_esrc[i + 1]);
        float2 v0 = *(const float2*)(x + (size_t)s0 * FN + lane * 2);
        float2 v1 = *(const float2*)(x + (size_t)s1 * FN + lane * 2);
        acc.x += v0.x + v1.x;
        acc.y += v0.y + v1.y;
    }
    if (i < end) {
        int s0 = __ldg(&g_esrc[i]);
        float2 v0 = *(const float2*)(x + (size_t)s0 * FN + lane * 2);
        acc.x += v0.x; acc.y += v0.y;
    }
    float inv = g_inv[n];
    *(float2*)(g_agg1 + (size_t)n * FN + lane * 2) = make_float2(acc.x * inv, acc.y * inv);
}

__global__ void agg2_kernel() {
    int warp = threadIdx.x >> 5, lane = threadIdx.x & 31;
    int n = blockIdx.x * 8 + warp;
    int beg = g_rowptr[n], end = g_rowptr[n + 1];
    float4 acc = make_float4(0.0f, 0.0f, 0.0f, 0.0f);
    int i = beg;
    for (; i + 1 < end; i += 2) {
        int s0 = __ldg(&g_esrc[i]);
        int s1 = __ldg(&g_esrc[i + 1]);
        float4 v0 = *(const float4*)(g_h1 + (size_t)s0 * HH + lane * 4);
        float4 v1 = *(const float4*)(g_h1 + (size_t)s1 * HH + lane * 4);
        acc.x += v0.x + v1.x; acc.y += v0.y + v1.y;
        acc.z += v0.z + v1.z; acc.w += v0.w + v1.w;
    }
    if (i < end) {
        int s0 = __ldg(&g_esrc[i]);
        float4 v0 = *(const float4*)(g_h1 + (size_t)s0 * HH + lane * 4);
        acc.x += v0.x; acc.y += v0.y; acc.z += v0.z; acc.w += v0.w;
    }
    float inv = g_inv[n];
    acc.x *= inv; acc.y *= inv; acc.z *= inv; acc.w *= inv;
    *(float4*)(g_agg2 + (size_t)n * HH + lane * 4) = acc;
}

// ============= tf32 mma.sync GEMMs ===========================================
// Output tile 128x128, block 256 thr (8 warps, 4x2), warp tile 32x64.
// B (weights) packed in fragment order: sBf[kstep][ntile(16)][lane]{b0,b1}.
//   b0 = W'[j][k], j = ntile*8 + (lane>>2), k = kstep*8 + (lane&3)
//   b1 = same with k+4.  (tf32 bits)
// A staged per tile: sA[128][132] uint32 tf32 bits.

// gemm1: K=128, A = [agg1 | x] (64+64), W' = [Wl1 ; Wr1]
__global__ void __launch_bounds__(256, 1)
mmagemm1_kernel(const float* __restrict__ x, const float* __restrict__ Wl,
                const float* __restrict__ Wr, const float* __restrict__ b1) {
    extern __shared__ char smem[];
    uint32_t* sBf = (uint32_t*)smem;                   // 16*16*32*2 = 16384 u32 = 64KB
    uint32_t* sA  = (uint32_t*)(smem + 65536);         // 128*132 u32 = 67584B
    float*    sBias = (float*)(smem + 65536 + 67584);  // 128 f
    int t = threadIdx.x;
    int wid = t >> 5, lane = t & 31;
    int g = lane >> 2, c = lane & 3;
    int wm = wid >> 1, wn = wid & 1;
    int r0 = wm * 32, jbase = wn * 64;

    // pack weights into fragment order (once per block)
    for (int i = t; i < 16 * 16 * 32; i += 256) {
        int lane_i = i & 31, nt = (i >> 5) & 15, ks = i >> 9;
        int j = nt * 8 + (lane_i >> 2);
        int k = ks * 8 + (lane_i & 3);
        const float* Wp0 = (k < 64) ? &Wl[j * 64 + k] : &Wr[j * 64 + k - 64];
        const float* Wp1 = (k + 4 < 64) ? &Wl[j * 64 + k + 4] : &Wr[j * 64 + k + 4 - 64];
        sBf[i * 2 + 0] = cvt_tf32(__ldg(Wp0));
        sBf[i * 2 + 1] = cvt_tf32(__ldg(Wp1));
    }
    if (t < 128) sBias[t] = __ldg(&b1[t]);
    __syncthreads();

    for (int tile = blockIdx.x; tile < NN / 128; tile += gridDim.x) {
        int row0 = tile * 128;
        __syncthreads();
        #pragma unroll
        for (int i = 0; i < 16; i++) {
            int idx = t + i * 256;            // 4096 float4 = 128 rows * 32 quads
            int r = idx >> 5, q = idx & 31;
            float4 v;
            if (q < 16) v = *(const float4*)(g_agg1 + (size_t)(row0 + r) * FN + q * 4);
            else        v = *(const float4*)(x + (size_t)(row0 + r) * FN + (q - 16) * 4);
            uint32_t* d = sA + r * 132 + q * 4;
            d[0] = cvt_tf32(v.x); d[1] = cvt_tf32(v.y); d[2] = cvt_tf32(v.z); d[3] = cvt_tf32(v.w);
        }
        __syncthreads();

        float4 acc[2][8];
        #pragma unroll
        for (int mt = 0; mt < 2; mt++)
            #pragma unroll
            for (int nt = 0; nt < 8; nt++) acc[mt][nt] = make_float4(0.f, 0.f, 0.f, 0.f);

        #pragma unroll
        for (int ks = 0; ks < 16; ks++) {
            int k0 = ks * 8;
            uint32_t a[2][4];
            #pragma unroll
            for (int mt = 0; mt < 2; mt++) {
                const uint32_t* base = sA + (r0 + mt * 16 + g) * 132 + k0 + c;
                a[mt][0] = base[0];
                a[mt][1] = base[8 * 132];
                a[mt][2] = base[4];
                a[mt][3] = base[8 * 132 + 4];
            }
            const uint32_t* bb = sBf + ((ks * 16 + wn * 8) * 32 + lane) * 2;
            #pragma unroll
            for (int nt = 0; nt < 8; nt++) {
                uint32_t b0 = bb[nt * 64], b1 = bb[nt * 64 + 1];
                mma_tf32(acc[0][nt], a[0], b0, b1);
                mma_tf32(acc[1][nt], a[1], b0, b1);
            }
        }

        #pragma unroll
        for (int mt = 0; mt < 2; mt++) {
            int m0 = row0 + r0 + mt * 16 + g;
            #pragma unroll
            for (int nt = 0; nt < 8; nt++) {
                int j = jbase + nt * 8 + 2 * c;
                float bx = sBias[j], by = sBias[j + 1];
                float4 ac = acc[mt][nt];
                float2 lo = make_float2(fmaxf(ac.x + bx, 0.f), fmaxf(ac.y + by, 0.f));
                float2 hi = make_float2(fmaxf(ac.z + bx, 0.f), fmaxf(ac.w + by, 0.f));
                *(float2*)(g_h1 + (size_t)m0 * HH + j) = lo;
                *(float2*)(g_h1 + (size_t)(m0 + 8) * HH + j) = hi;
            }
        }
    }
}

// gemm2: K=256 in two halves (agg2/Wl2 then h1/Wr2)
__global__ void __launch_bounds__(256, 1)
mmagemm2_kernel(const float* __restrict__ Wl, const float* __restrict__ Wr,
                const float* __restrict__ b2) {
    extern __shared__ char smem[];
    uint32_t* sBf = (uint32_t*)smem;                     // 32*16*32*2 u32 = 128KB
    uint32_t* sA  = (uint32_t*)(smem + 131072);          // 67584B
    float*    sBias = (float*)(smem + 131072 + 67584);
    int t = threadIdx.x;
    int wid = t >> 5, lane = t & 31;
    int g = lane >> 2, c = lane & 3;
    int wm = wid >> 1, wn = wid & 1;
    int r0 = wm * 32, jbase = wn * 64;

    for (int i = t; i < 32 * 16 * 32; i += 256) {
        int lane_i = i & 31, nt = (i >> 5) & 15, ks = i >> 9;
        int j = nt * 8 + (lane_i >> 2);
        int k = ks * 8 + (lane_i & 3);
        const float* Wp0 = (k < 128) ? &Wl[j * 128 + k] : &Wr[j * 128 + k - 128];
        const float* Wp1 = (k + 4 < 128) ? &Wl[j * 128 + k + 4] : &Wr[j * 128 + k + 4 - 128];
        sBf[i * 2 + 0] = cvt_tf32(__ldg(Wp0));
        sBf[i * 2 + 1] = cvt_tf32(__ldg(Wp1));
    }
    if (t < 128) sBias[t] = __ldg(&b2[t]);
    __syncthreads();

    for (int tile = blockIdx.x; tile < NN / 128; tile += gridDim.x) {
        int row0 = tile * 128;
        float4 acc[2][8];
        #pragma unroll
        for (int mt = 0; mt < 2; mt++)
            #pragma unroll
            for (int nt = 0; nt < 8; nt++) acc[mt][nt] = make_float4(0.f, 0.f, 0.f, 0.f);

        #pragma unroll 1
        for (int kh = 0; kh < 2; kh++) {
            const float* srcA = kh ? g_h1 : g_agg2;
            __syncthreads();
            #pragma unroll
            for (int i = 0; i < 16; i++) {
                int idx = t + i * 256;
                int r = idx >> 5, q = idx & 31;
                float4 v = *(const float4*)(srcA + (size_t)(row0 + r) * HH + q * 4);
                uint32_t* d = sA + r * 132 + q * 4;
                d[0] = cvt_tf32(v.x); d[1] = cvt_tf32(v.y); d[2] = cvt_tf32(v.z); d[3] = cvt_tf32(v.w);
            }
            __syncthreads();

            #pragma unroll
            for (int ks = 0; ks < 16; ks++) {
                int k0 = ks * 8;
                uint32_t a[2][4];
                #pragma unroll
                for (int mt = 0; mt < 2; mt++) {
                    const uint32_t* base = sA + (r0 + mt * 16 + g) * 132 + k0 + c;
                    a[mt][0] = base[0];
                    a[mt][1] = base[8 * 132];
                    a[mt][2] = base[4];
                    a[mt][3] = base[8 * 132 + 4];
                }
                const uint32_t* bb = sBf + (((kh * 16 + ks) * 16 + wn * 8) * 32 + lane) * 2;
                #pragma unroll
                for (int nt = 0; nt < 8; nt++) {
                    uint32_t b0 = bb[nt * 64], b1 = bb[nt * 64 + 1];
                    mma_tf32(acc[0][nt], a[0], b0, b1);
                    mma_tf32(acc[1][nt], a[1], b0, b1);
                }
            }
        }

        #pragma unroll
        for (int mt = 0; mt < 2; mt++) {
            int m0 = row0 + r0 + mt * 16 + g;
            #pragma unroll
            for (int nt = 0; nt < 8; nt++) {
                int j = jbase + nt * 8 + 2 * c;
                float bx = sBias[j], by = sBias[j + 1];
                float4 ac = acc[mt][nt];
                float2 lo = make_float2(fmaxf(ac.x + bx, 0.f), fmaxf(ac.y + by, 0.f));
                float2 hi = make_float2(fmaxf(ac.z + bx, 0.f), fmaxf(ac.w + by, 0.f));
                *(float2*)(g_nemb + (size_t)m0 * HH + j) = lo;
                *(float2*)(g_nemb + (size_t)(m0 + 8) * HH + j) = hi;
            }
        }
    }
}

// ---------------- graph mean pooling -----------------------------------------
__global__ void pool_kernel(const int* __restrict__ batch) {
    int j = threadIdx.x;
    int n0 = blockIdx.x * 256;
    float sum = 0.0f, cc = 0.0f;
    int cur = __ldg(&batch[n0]);
    for (int r = 0; r < 256; r++) {
        int b = __ldg(&batch[n0 + r]);
        if (b != cur) {
            atomicAdd(&g_gsum[cur * HH + j], sum);
            if (j == 0) atomicAdd(&g_gcnt[cur], cc);
            sum = 0.0f; cc = 0.0f; cur = b;
        }
        sum += g_nemb[(size_t)(n0 + r) * HH + j];
        cc += 1.0f;
    }
    atomicAdd(&g_gsum[cur * HH + j], sum);
    if (j == 0) atomicAdd(&g_gcnt[cur], cc);
}

// ---------------- Whh transpose ----------------------------------------------
__global__ void transpose_whh(const float* __restrict__ Whh) {
    int idx = blockIdx.x * 256 + threadIdx.x;
    int j = idx >> 7, k = idx & 127;
    g_WT[k * 512 + j] = Whh[idx];
}

// ---------------- LSTM input GEMM (SIMT) -------------------------------------
__global__ void xg_gemm_kernel(const int* __restrict__ path_idx, const float* __restrict__ Wih,
                               const float* __restrict__ bih, const float* __restrict__ bhh) {
    extern __shared__ float sm[];
    float* sW = sm;                   // [128][132]
    float* sIn = sm + 128 * 132;      // [64][128]
    __shared__ int snode[64];
    int t = threadIdx.x;
    int jbase = blockIdx.y * 128;
    #pragma unroll 4
    for (int i = 0; i < 64; i++) {
        int idx = t + i * 256;
        int j = idx >> 7, k = idx & 127;
        sW[k * 132 + j] = __ldg(&Wih[(size_t)(jbase + j) * 128 + k]);
    }
    int j4 = t & 31, r0 = (t >> 5) * 8;
    float4 bias;
    {
        float4 a = *(const float4*)(bih + jbase + j4 * 4);
        float4 b = *(const float4*)(bhh + jbase + j4 * 4);
        bias = make_float4(a.x + b.x, a.y + b.y, a.z + b.z, a.w + b.w);
    }
    int row0 = blockIdx.x * 64;
    if (t < 64) snode[t] = __ldg(&path_idx[row0 + t]);
    __syncthreads();
    #pragma unroll
    for (int i = 0; i < 8; i++) {
        int idx = t + i * 256;
        int r = idx >> 5, kq = idx & 31;
        int node = snode[r];
        float4 v = *(const float4*)(g_nemb + (size_t)node * HH + kq * 4);
        *(float4*)(sIn + r * 128 + kq * 4) = v;
    }
    __syncthreads();
    float4 acc[8];
    #pragma unroll
    for (int r = 0; r < 8; r++) acc[r] = bias;
    #pragma unroll 2
    for (int k = 0; k < 128; k += 4) {
        float4 w0 = *(const float4*)(sW + (k + 0) * 132 + j4 * 4);
        float4 w1 = *(const float4*)(sW + (k + 1) * 132 + j4 * 4);
        float4 w2 = *(const float4*)(sW + (k + 2) * 132 + j4 * 4);
        float4 w3 = *(const float4*)(sW + (k + 3) * 132 + j4 * 4);
        #pragma unroll
        for (int r = 0; r < 8; r++) {
            float4 a = *(const float4*)(sIn + (r0 + r) * 128 + k);
            acc[r].x += a.x * w0.x; acc[r].y += a.x * w0.y; acc[r].z += a.x * w0.z; acc[r].w += a.x * w0.w;
            acc[r].x += a.y * w1.x; acc[r].y += a.y * w1.y; acc[r].z += a.y * w1.z; acc[r].w += a.y * w1.w;
            acc[r].x += a.z * w2.x; acc[r].y += a.z * w2.y; acc[r].z += a.z * w2.z; acc[r].w += a.z * w2.w;
            acc[r].x += a.w * w3.x; acc[r].y += a.w * w3.y; acc[r].z += a.w * w3.z; acc[r].w += a.w * w3.w;
        }
    }
    #pragma unroll
    for (int r = 0; r < 8; r++)
        *(float4*)(g_Xg + (size_t)(row0 + r0 + r) * 512 + jbase + j4 * 4) = acc[r];
}

// ---------------- LSTM recurrence --------------------------------------------
__global__ void lstm_kernel(const int* __restrict__ path_len) {
    __shared__ float sh[4 * 128];
    __shared__ float scm[4 * 128];
    __shared__ float sG[4 * 512];
    __shared__ int splen[4];
    int t = threadIdx.x;
    int b0 = blockIdx.x * 4;
    for (int i = t; i < 512; i += 256) { sh[i] = 0.0f; scm[i] = 0.0f; }
    if (t < 4) splen[t] = path_len[b0 + t];
    __syncthreads();
    int half = t >> 7;
    int jq = t & 127;
    int bA = half * 2, bB = half * 2 + 1;
    for (int step = 0; step < LL; step++) {
        float4 a0 = *(const float4*)(g_Xg + ((size_t)(b0 + bA) * LL + step) * 512 + jq * 4);
        float4 a1 = *(const float4*)(g_Xg + ((size_t)(b0 + bB) * LL + step) * 512 + jq * 4);
        #pragma unroll 4
        for (int k = 0; k < 128; k++) {
            float4 w = *(const float4*)(g_WT + k * 512 + jq * 4);
            float hA = sh[bA * 128 + k];
            float hB = sh[bB * 128 + k];
            a0.x += w.x * hA; a0.y += w.y * hA; a0.z += w.z * hA; a0.w += w.w * hA;
            a1.x += w.x * hB; a1.y += w.y * hB; a1.z += w.z * hB; a1.w += w.w * hB;
        }
        *(float4*)(sG + bA * 512 + jq * 4) = a0;
        *(float4*)(sG + bB * 512 + jq * 4) = a1;
        __syncthreads();
        #pragma unroll
        for (int u = 0; u < 2; u++) {
            int idx = t + u * 256;
            int b = idx >> 7, j = idx & 127;
            float ig = sG[b * 512 + j];
            float fg = sG[b * 512 + 128 + j];
            float gg = sG[b * 512 + 256 + j];
            float og = sG[b * 512 + 384 + j];
            float cn = sigf(fg) * scm[b * 128 + j] + sigf(ig) * tanhf(gg);
            float hn = sigf(og) * tanhf(cn);
            if (step < splen[b]) { scm[b * 128 + j] = cn; sh[b * 128 + j] = hn; }
        }
        __syncthreads();
    }
    for (int i = t; i < 512; i += 256) g_pemb[b0 * 128 + i] = sh[i];
}

// ---------------- scoring head -----------------------------------------------
__global__ void head_kernel(const float* __restrict__ flow, const float* __restrict__ Wf,
                            const float* __restrict__ bf, const float* __restrict__ Ws1,
                            const float* __restrict__ bs1, const float* __restrict__ Ws2,
                            const float* __restrict__ bs2, float* __restrict__ out) {
    __shared__ float comb[320];
    __shared__ float red_[128];
    int b = blockIdx.x, j = threadIdx.x;
    comb[j] = g_gsum[b * HH + j] * (1.0f / fmaxf(g_gcnt[b], 1.0f));
    comb[128 + j] = g_pemb[b * HH + j];
    if (j < 64) {
        float a = __ldg(&bf[j]);
        #pragma unroll
        for (int k = 0; k < FF; k++) a += flow[b * FF + k] * Wf[j * FF + k];
        comb[256 + j] = fmaxf(a, 0.0f);
    }
    __syncthreads();
    float acc = __ldg(&bs1[j]);
    const float4* wr = (const float4*)(Ws1 + (size_t)j * 320);
    const float4* cb = (const float4*)comb;
    #pragma unroll 8
    for (int k = 0; k < 80; k++) {
        float4 w = wr[k], c = cb[k];
        acc += w.x * c.x + w.y * c.y + w.z * c.z + w.w * c.w;
    }
    float h = fmaxf(acc, 0.0f);
    red_[j] = h * __ldg(&Ws2[j]);
    __syncthreads();
    for (int s = 64; s > 0; s >>= 1) {
        if (j < s) red_[j] += red_[j + s];
        __syncthreads();
    }
    if (j == 0) out[b] = red_[0] + __ldg(&bs2[0]);
}

// ---------------- launch ------------------------------------------------------
extern "C" void kernel_launch(void* const* d_in, const int* in_sizes, int n_in,
                              void* d_out, int out_size) {
    const float* x        = (const float*)d_in[0];
    const int*   ei       = (const int*)d_in[1];
    const int*   batch    = (const int*)d_in[2];
    const int*   path_idx = (const int*)d_in[3];
    const int*   path_len = (const int*)d_in[4];
    const float* flow     = (const float*)d_in[5];
    const float* Wl1 = (const float*)d_in[6];
    const float* Wr1 = (const float*)d_in[7];
    const float* b1  = (const float*)d_in[8];
    const float* Wl2 = (const float*)d_in[9];
    const float* Wr2 = (const float*)d_in[10];
    const float* b2  = (const float*)d_in[11];
    const float* Wih = (const float*)d_in[12];
    const float* Whh = (const float*)d_in[13];
    const float* bih = (const float*)d_in[14];
    const float* bhh = (const float*)d_in[15];
    const float* Wf  = (const float*)d_in[16];
    const float* bf  = (const float*)d_in[17];
    const float* Ws1 = (const float*)d_in[18];
    const float* bs1 = (const float*)d_in[19];
    const float* Ws2 = (const float*)d_in[20];
    const float* bs2 = (const float*)d_in[21];
    float* out = (float*)d_out;

    const int SMG1 = 65536 + 67584 + 512;    // 133632
    const int SMG2 = 131072 + 67584 + 512;   // 199168
    const int XGSM = (128 * 132 + 64 * 128) * 4;
    cudaFuncSetAttribute(mmagemm1_kernel, cudaFuncAttributeMaxDynamicSharedMemorySize, SMG1);
    cudaFuncSetAttribute(mmagemm2_kernel, cudaFuncAttributeMaxDynamicSharedMemorySize, SMG2);
    cudaFuncSetAttribute(xg_gemm_kernel,  cudaFuncAttributeMaxDynamicSharedMemorySize, XGSM);

    zero_small<<<512, 256>>>();
    count_kernel<<<8192, 256>>>(ei);
    blocksum_kernel<<<512, 256>>>();
    scan512_kernel<<<1, 512>>>();
    rowptr_kernel<<<512, 256>>>();
    escatter_kernel<<<8192, 256>>>(ei);
    agg1_kernel<<<16384, 256>>>(x);
    mmagemm1_kernel<<<148, 256, SMG1>>>(x, Wl1, Wr1, b1);
    agg2_kernel<<<16384, 256>>>();
    mmagemm2_kernel<<<148, 256, SMG2>>>(Wl2, Wr2, b2);
    pool_kernel<<<512, 128>>>(batch);
    transpose_whh<<<256, 256>>>(Whh);
    xg_gemm_kernel<<<dim3(128, 4), 256, XGSM>>>(path_idx, Wih, bih, bhh);
    lstm_kernel<<<64, 256>>>(path_len);
    head_kernel<<<256, 128>>>(flow, Wf, bf, Ws1, bs1, Ws2, bs2, out);
}